// round 1
// baseline (speedup 1.0000x reference)
#include <cuda_runtime.h>

// RawISPProcessing: demosaic (2x bilinear, flips are exact no-ops) + fused
// channel-flip/awb/ccm 3x3 matrix + gamma, applied to both pred and gt.
//
// Input  : pred (8,4,512,512) f32, gt (8,4,512,512) f32, awb (8,3,3), cam2rgb (8,3,3), rgb_gain (unused)
// Output : x (8,3,1024,1024) f32 followed by y (8,3,1024,1024) f32

#define HIN  512
#define WIN  512
#define PLANE (HIN * WIN)          // 262144
#define OPLANE (1024 * 1024)       // per-channel output plane

__device__ float g_A[8 * 9];       // fused per-batch matrix (includes *2 and both channel flips)

__global__ void prep_mat_kernel(const float* __restrict__ awb,
                                const float* __restrict__ ccm) {
    int t = threadIdx.x;           // 72 threads: 8 batches x 9 entries
    if (t >= 72) return;
    int b = t / 9;
    int r = t % 9;
    int j = r / 3;                 // input RGB channel
    int c = r % 3;                 // output RGB channel
    const float* Aw = awb + b * 9;
    const float* Cm = ccm + b * 9;
    float s = 0.0f;
#pragma unroll
    for (int m = 0; m < 3; m++)
        s += Aw[(2 - j) * 3 + m] * Cm[m * 3 + (2 - c)];
    g_A[t] = 2.0f * s;
}

__device__ __forceinline__ float gamma_pow(float v) {
    v = fmaxf(v, 1e-8f);
    float l;
    asm("lg2.approx.f32 %0, %1;" : "=f"(l) : "f"(v));
    l *= 0.45454545454545453f;     // 1/2.2
    float r;
    asm("ex2.approx.f32 %0, %1;" : "=f"(r) : "f"(l));
    return r;
}

// 2x bilinear upsample of one plane at the 2x2 output block owned by (h,w).
// Row offsets (hm,h0,hp already *WIN) and clamped cols (wm,w,wp) are shared
// across the 4 channel planes.
// Returns: x=(dy0,dx0) y=(dy0,dx1) z=(dy1,dx0) w=(dy1,dx1)
__device__ __forceinline__ float4 up2x2(const float* __restrict__ p,
                                        int hm, int h0, int hp,
                                        int wm, int w, int wp) {
    float a00 = p[hm + wm], a01 = p[hm + w], a02 = p[hm + wp];
    float a10 = p[h0 + wm], a11 = p[h0 + w], a12 = p[h0 + wp];
    float a20 = p[hp + wm], a21 = p[hp + w], a22 = p[hp + wp];
    // horizontal interp per tap row
    float r0x0 = 0.25f * a00 + 0.75f * a01, r0x1 = 0.75f * a01 + 0.25f * a02;
    float r1x0 = 0.25f * a10 + 0.75f * a11, r1x1 = 0.75f * a11 + 0.25f * a12;
    float r2x0 = 0.25f * a20 + 0.75f * a21, r2x1 = 0.75f * a21 + 0.25f * a22;
    float4 u;
    u.x = 0.25f * r0x0 + 0.75f * r1x0;
    u.y = 0.25f * r0x1 + 0.75f * r1x1;
    u.z = 0.75f * r1x0 + 0.25f * r2x0;
    u.w = 0.75f * r1x1 + 0.25f * r2x1;
    return u;
}

__global__ __launch_bounds__(256)
void isp_kernel(const float* __restrict__ pred,
                const float* __restrict__ gt,
                float* __restrict__ out) {
    const int w = blockIdx.x * 32 + threadIdx.x;   // input col 0..511
    const int h = blockIdx.y * 8 + threadIdx.y;    // input row 0..511
    const int z = blockIdx.z;                      // 0..15
    const int which = z >> 3;                      // 0 = pred->x, 1 = gt->y
    const int b = z & 7;

    const float* __restrict__ img =
        (which ? gt : pred) + (size_t)b * (4 * PLANE);

    float A[9];
#pragma unroll
    for (int i = 0; i < 9; i++) A[i] = g_A[b * 9 + i];

    const int hm = max(h - 1, 0) * WIN;
    const int h0 = h * WIN;
    const int hp = min(h + 1, HIN - 1) * WIN;
    const int wm = max(w - 1, 0);
    const int wp = min(w + 1, WIN - 1);

    float4 R  = up2x2(img + 0 * PLANE, hm, h0, hp, wm, w, wp);
    float4 GR = up2x2(img + 1 * PLANE, hm, h0, hp, wm, w, wp);
    float4 GB = up2x2(img + 2 * PLANE, hm, h0, hp, wm, w, wp);
    float4 Bl = up2x2(img + 3 * PLANE, hm, h0, hp, wm, w, wp);

    // green mosaic: (ee)+(oo) = avg, (eo) = gr, (oe) = gb
    float G00 = 0.5f * (GR.x + GB.x);
    float G01 = GR.y;
    float G10 = GB.z;
    float G11 = 0.5f * (GR.w + GB.w);

    float r4[4] = {R.x, R.y, R.z, R.w};
    float g4[4] = {G00, G01, G10, G11};
    float b4[4] = {Bl.x, Bl.y, Bl.z, Bl.w};

    const size_t obase = ((size_t)which * 8 + b) * (3 * (size_t)OPLANE);
    // float2 stores: row (2h+dy) of channel c, columns 2w..2w+1
#pragma unroll
    for (int c = 0; c < 3; c++) {
        float v00 = gamma_pow(A[c] * r4[0] + A[3 + c] * g4[0] + A[6 + c] * b4[0]);
        float v01 = gamma_pow(A[c] * r4[1] + A[3 + c] * g4[1] + A[6 + c] * b4[1]);
        float v10 = gamma_pow(A[c] * r4[2] + A[3 + c] * g4[2] + A[6 + c] * b4[2]);
        float v11 = gamma_pow(A[c] * r4[3] + A[3 + c] * g4[3] + A[6 + c] * b4[3]);

        size_t rowbase = obase + (size_t)c * OPLANE;
        float2* o0 = (float2*)(out + rowbase + (size_t)(2 * h) * 1024) + w;
        float2* o1 = (float2*)(out + rowbase + (size_t)(2 * h + 1) * 1024) + w;
        *o0 = make_float2(v00, v01);
        *o1 = make_float2(v10, v11);
    }
}

extern "C" void kernel_launch(void* const* d_in, const int* in_sizes, int n_in,
                              void* d_out, int out_size) {
    const float* pred = (const float*)d_in[0];
    const float* gt   = (const float*)d_in[1];
    const float* awb  = (const float*)d_in[2];
    const float* ccm  = (const float*)d_in[3];
    // d_in[4] = rgb_gain: unused by the reference

    prep_mat_kernel<<<1, 72>>>(awb, ccm);

    dim3 blk(32, 8);
    dim3 grd(WIN / 32, HIN / 8, 16);
    isp_kernel<<<grd, blk>>>(pred, gt, (float*)d_out);
}